// round 1
// baseline (speedup 1.0000x reference)
#include <cuda_runtime.h>

#define BB   8
#define NN   2048
#define CC   64
#define MIDD 256
#define KK   16
#define R2   0.0225f
#define EPSV 1e-5f

// ---------------- device scratch (no allocations allowed) ----------------
__device__ float d_h[BB*NN*CC];        // h[b][n][o] = w1[:,3:]·f + w1[:,:3]·p   (4 MB)
__device__ int   d_idx[BB*NN*KK];      // neighbor indices (within batch)        (1 MB)
__device__ float d_xmax[BB*NN*CC];     // max_k of raw conv output               (4 MB)
__device__ float d_y[BB*NN*MIDD];      // pre-BN2 mlp2 output                    (16.8 MB)
__device__ float d_z[BB*CC*NN];        // pre-BN3 mlp3 output, (B,C,N) layout    (4 MB)
__device__ float d_w2T[MIDD*CC];       // w2 transposed: [c][m]
__device__ float d_w3T[CC*MIDD];       // w3 transposed: [c][o]
// stats layout: sum1[64] sq1[64] sum2[256] sq2[256] sum3[64] sq3[64]
__device__ float d_stats[768];
// scale/bias layout: s1[64] t1[64] s2[256] t2[256] s3[64] t3[64]
__device__ float d_sb[768];

// ---------------- prep: zero stats + transpose weights ----------------
__global__ void prep_kernel(const float* __restrict__ w2, const float* __restrict__ w3) {
    int i = blockIdx.x * blockDim.x + threadIdx.x;   // grid 64x256 = 16384
    if (i < 768) d_stats[i] = 0.f;
    if (i < MIDD*CC) {                // w2 is (MIDD, CC) row-major
        int m = i / CC, c = i % CC;
        d_w2T[c*MIDD + m] = w2[i];
    }
    if (i < CC*MIDD) {                // w3 is (CC, MIDD) row-major
        int o = i / MIDD, c = i % MIDD;
        d_w3T[c*CC + o] = w3[i];
    }
}

// ---------------- ball query: first K indices (ascending) within radius ----------------
__global__ void bq_kernel(const float* __restrict__ p) {
    __shared__ float sx[NN], sy[NN], sz[NN];
    int b    = blockIdx.x >> 4;       // grid = B*16 = 128, blockDim = 128
    int tile = blockIdx.x & 15;
    const float* pb = p + b*NN*3;
    for (int j = threadIdx.x; j < NN; j += blockDim.x) {
        sx[j] = pb[3*j]; sy[j] = pb[3*j+1]; sz[j] = pb[3*j+2];
    }
    __syncthreads();
    int n = tile*128 + threadIdx.x;
    float qx = sx[n], qy = sy[n], qz = sz[n];
    int* out = d_idx + (b*NN + n)*KK;
    int cnt = 0, first = 0;
    for (int j = 0; j < NN; j++) {
        float dx = sx[j]-qx, dy = sy[j]-qy, dz = sz[j]-qz;
        float d2 = dx*dx + dy*dy + dz*dz;
        if (d2 < R2) {
            if (cnt == 0) first = j;
            out[cnt] = j;
            cnt++;
            if (cnt >= KK) break;
        }
    }
    for (int k = cnt; k < KK; k++) out[k] = first;   // pad with first (matches reference)
}

// ---------------- h precompute: h[b][n][o] = w1[o,3:]·f[b,:,n] + w1[o,:3]·p[b,n] ----------------
__global__ void hpre_kernel(const float* __restrict__ p, const float* __restrict__ f,
                            const float* __restrict__ w1) {
    __shared__ float ft[CC][32];
    __shared__ float pt[32][3];
    __shared__ float sw1[CC*67];
    int b  = blockIdx.x >> 6;          // grid = 8*64 = 512, blockDim = 256
    int n0 = (blockIdx.x & 63) * 32;
    int t  = threadIdx.x;
    for (int i = t; i < CC*67; i += 256) sw1[i] = w1[i];
    for (int i = t; i < CC*32; i += 256) {
        int c = i >> 5, j = i & 31;
        ft[c][j] = f[(b*CC + c)*NN + n0 + j];
    }
    for (int i = t; i < 96; i += 256) {
        int j = i/3, d = i%3;
        pt[j][d] = p[(b*NN + n0 + j)*3 + d];
    }
    __syncthreads();
    int o = t & 63, pg = t >> 6;
    const float* wrow = &sw1[o*67];
    for (int j = pg; j < 32; j += 4) {
        float acc = wrow[0]*pt[j][0] + wrow[1]*pt[j][1] + wrow[2]*pt[j][2];
        #pragma unroll
        for (int c = 0; c < CC; c++) acc += wrow[3+c]*ft[c][j];
        d_h[(b*NN + n0 + j)*CC + o] = acc;
    }
}

// ---------------- gather + max_k + BN1 stats ----------------
__global__ void group_kernel(const float* __restrict__ p, const float* __restrict__ w1) {
    __shared__ int   sidx[16][KK];
    __shared__ float spc[16][3];
    __shared__ float sw1p[CC][3];
    __shared__ float rsum[4][CC], rsq[4][CC];
    int t    = threadIdx.x;            // 256
    int base = blockIdx.x * 16;        // grid = B*N/16 = 1024; 2048%16==0 so no batch straddle
    int b    = base / NN;
    for (int i = t; i < 16*KK; i += 256) {
        int pt_ = i >> 4, k = i & 15;
        sidx[pt_][k] = d_idx[(base + pt_)*KK + k];
    }
    if (t < 48) { int j = t/3, d = t%3; spc[j][d] = p[(base + j)*3 + d]; }
    if (t < CC*3) sw1p[t/3][t%3] = w1[(t/3)*67 + (t%3)];
    __syncthreads();
    int o = t & 63, pg = t >> 6;
    float w0 = sw1p[o][0], w1c = sw1p[o][1], w2c = sw1p[o][2];
    float ssum = 0.f, ssq = 0.f;
    for (int j = pg; j < 16; j += 4) {
        float q  = w0*spc[j][0] + w1c*spc[j][1] + w2c*spc[j][2];
        float mx = -1e30f;
        #pragma unroll
        for (int k = 0; k < KK; k++) {
            int nb  = sidx[j][k];
            float v = d_h[(b*NN + nb)*CC + o] - q;
            mx = fmaxf(mx, v);
            ssum += v;
            ssq  += v*v;
        }
        d_xmax[(base + j)*CC + o] = mx;
    }
    rsum[pg][o] = ssum; rsq[pg][o] = ssq;
    __syncthreads();
    if (t < CC) {
        float s = rsum[0][t]+rsum[1][t]+rsum[2][t]+rsum[3][t];
        float q = rsq[0][t]+rsq[1][t]+rsq[2][t]+rsq[3][t];
        atomicAdd(&d_stats[t],      s);
        atomicAdd(&d_stats[CC + t], q);
    }
}

__global__ void fin1_kernel(const float* __restrict__ g1, const float* __restrict__ b1) {
    int o = threadIdx.x;  // 64
    float cnt  = (float)(BB*NN*KK);
    float mean = d_stats[o] / cnt;
    float var  = d_stats[CC + o] / cnt - mean*mean;
    float s = g1[o] * rsqrtf(var + EPSV);
    d_sb[o]      = s;
    d_sb[CC + o] = b1[o] - mean*s;
}

// ---------------- mlp2: y = w2 @ relu(bn1(xmax)), + BN2 stats ----------------
__global__ void mlp2_kernel() {
    __shared__ float a[CC];
    int t    = threadIdx.x;            // 256 (one output channel m per thread)
    int base = blockIdx.x * 32;        // grid = B*N/32 = 512
    float w[CC];
    #pragma unroll
    for (int c = 0; c < CC; c++) w[c] = d_w2T[c*MIDD + t];   // column m of w2, register-resident
    float ssum = 0.f, ssq = 0.f;
    for (int pp = 0; pp < 32; pp++) {
        int pidx = base + pp;
        if (t < CC) {
            float v = d_sb[t]*d_xmax[pidx*CC + t] + d_sb[CC + t];
            a[t] = fmaxf(v, 0.f);
        }
        __syncthreads();
        float acc = 0.f;
        #pragma unroll
        for (int c = 0; c < CC; c++) acc += w[c]*a[c];
        d_y[pidx*MIDD + t] = acc;
        ssum += acc; ssq += acc*acc;
        __syncthreads();
    }
    atomicAdd(&d_stats[128 + t], ssum);
    atomicAdd(&d_stats[384 + t], ssq);
}

__global__ void fin2_kernel(const float* __restrict__ g2, const float* __restrict__ b2) {
    int m = threadIdx.x;  // 256
    float cnt  = (float)(BB*NN);
    float mean = d_stats[128 + m] / cnt;
    float var  = d_stats[384 + m] / cnt - mean*mean;
    float s = g2[m] * rsqrtf(var + EPSV);
    d_sb[128 + m] = s;
    d_sb[384 + m] = b2[m] - mean*s;
}

// ---------------- mlp3: z = w3 @ relu(bn2(y)), + BN3 stats, output (B,C,N) ----------------
__global__ void mlp3_kernel() {
    __shared__ float yb[MIDD];
    __shared__ float part[4][CC];
    __shared__ float zsm[CC][33];
    int t    = threadIdx.x;            // 256
    int o    = t & 63, cs = t >> 6;    // thread handles c-slice cs (64 of 256) for channel o
    int base = blockIdx.x * 32;        // grid = 512; 2048%32==0 so no batch straddle
    int b    = base / NN, n0 = base % NN;
    float wreg[64];
    #pragma unroll
    for (int cq = 0; cq < 64; cq++) wreg[cq] = d_w3T[(cs*64 + cq)*CC + o];
    float ssum = 0.f, ssq = 0.f;
    for (int pp = 0; pp < 32; pp++) {
        int pidx = base + pp;
        float v = d_sb[128 + t]*d_y[pidx*MIDD + t] + d_sb[384 + t];
        yb[t] = fmaxf(v, 0.f);
        __syncthreads();
        float acc = 0.f;
        #pragma unroll
        for (int cq = 0; cq < 64; cq++) acc += wreg[cq]*yb[cs*64 + cq];
        part[cs][o] = acc;
        __syncthreads();
        if (t < CC) {
            float z = part[0][t]+part[1][t]+part[2][t]+part[3][t];
            zsm[t][pp] = z;
            ssum += z; ssq += z*z;
        }
        // no extra sync needed: next iteration's first __syncthreads orders part rewrite
    }
    __syncthreads();
    for (int i = t; i < CC*32; i += 256) {
        int r = i >> 5, cl = i & 31;
        d_z[(b*CC + r)*NN + n0 + cl] = zsm[r][cl];
    }
    if (t < CC) {
        atomicAdd(&d_stats[640 + t], ssum);
        atomicAdd(&d_stats[704 + t], ssq);
    }
}

__global__ void fin3_kernel(const float* __restrict__ g3, const float* __restrict__ b3) {
    int o = threadIdx.x;  // 64
    float cnt  = (float)(BB*NN);
    float mean = d_stats[640 + o] / cnt;
    float var  = d_stats[704 + o] / cnt - mean*mean;
    float s = g3[o] * rsqrtf(var + EPSV);
    d_sb[640 + o] = s;
    d_sb[704 + o] = b3[o] - mean*s;
}

// ---------------- epilogue: out = relu(bn3(z) + f) ----------------
__global__ void out_kernel(const float* __restrict__ f, float* __restrict__ out) {
    int i = blockIdx.x * blockDim.x + threadIdx.x;   // grid 4096x256 = 1M
    int c = (i >> 11) & 63;
    float v = d_sb[640 + c]*d_z[i] + d_sb[704 + c] + f[i];
    out[i] = fmaxf(v, 0.f);
}

// ---------------- launch ----------------
extern "C" void kernel_launch(void* const* d_in, const int* in_sizes, int n_in,
                              void* d_out, int out_size) {
    const float* p  = (const float*)d_in[0];
    const float* f  = (const float*)d_in[1];
    const float* w1 = (const float*)d_in[2];
    const float* g1 = (const float*)d_in[3];
    const float* b1 = (const float*)d_in[4];
    const float* w2 = (const float*)d_in[5];
    const float* g2 = (const float*)d_in[6];
    const float* b2 = (const float*)d_in[7];
    const float* w3 = (const float*)d_in[8];
    const float* g3 = (const float*)d_in[9];
    const float* b3 = (const float*)d_in[10];
    float* out = (float*)d_out;

    prep_kernel <<<64, 256>>>(w2, w3);
    bq_kernel   <<<BB*16, 128>>>(p);
    hpre_kernel <<<BB*(NN/32), 256>>>(p, f, w1);
    group_kernel<<<BB*NN/16, 256>>>(p, w1);
    fin1_kernel <<<1, 64>>>(g1, b1);
    mlp2_kernel <<<BB*NN/32, 256>>>();
    fin2_kernel <<<1, 256>>>(g2, b2);
    mlp3_kernel <<<BB*NN/32, 256>>>();
    fin3_kernel <<<1, 64>>>(g3, b3);
    out_kernel  <<<BB*CC*NN/256, 256>>>(f, out);
}

// round 2
// speedup vs baseline: 1.3976x; 1.3976x over previous
#include <cuda_runtime.h>

#define BB   8
#define NN   2048
#define CC   64
#define MIDD 256
#define KK   16
#define R2   0.0225f
#define EPSV 1e-5f

// ---------------- device scratch ----------------
__device__ float d_h[BB*NN*CC];        // h[b][n][o]
__device__ int   d_idx[BB*NN*KK];
__device__ float d_xmax[BB*NN*CC];
__device__ float d_y[BB*NN*MIDD];
__device__ float d_z[BB*CC*NN];
__device__ float d_w2T[MIDD*CC];       // [c][m]
__device__ float d_w3T[CC*MIDD];       // [c][o]
__device__ float d_stats[768];         // sum1[64] sq1[64] sum2[256] sq2[256] sum3[64] sq3[64]
__device__ float d_sb[768];            // s1 t1 s2 t2 s3 t3

// ---------------- prep ----------------
__global__ void prep_kernel(const float* __restrict__ w2, const float* __restrict__ w3) {
    int i = blockIdx.x * blockDim.x + threadIdx.x;   // 64x256
    if (i < 768) d_stats[i] = 0.f;
    if (i < MIDD*CC) {
        int m = i / CC, c = i % CC;
        d_w2T[c*MIDD + m] = w2[i];
    }
    if (i < CC*MIDD) {
        int o = i / MIDD, c = i % MIDD;
        d_w3T[c*CC + o] = w3[i];
    }
}

// ---------------- ball query: warp-cooperative ballot scan ----------------
// One warp handles 8 queries; 32 candidate points tested per loop step.
// Ballot + prefix-popc compaction preserves ascending-index order exactly.
__global__ void bq_kernel(const float* __restrict__ p) {
    __shared__ float sx[NN], sy[NN], sz[NN];
    int b   = blockIdx.x >> 5;          // grid = BB*32 = 256 blocks, 256 threads
    int blk = blockIdx.x & 31;
    const float* pb = p + b*NN*3;
    for (int j = threadIdx.x; j < NN; j += 256) {
        sx[j] = pb[3*j]; sy[j] = pb[3*j+1]; sz[j] = pb[3*j+2];
    }
    __syncthreads();
    int w = threadIdx.x >> 5, lane = threadIdx.x & 31;
    int qbase = blk*64 + w*8;
    for (int q = 0; q < 8; q++) {
        int n = qbase + q;
        float qx = sx[n], qy = sy[n], qz = sz[n];
        int* out = d_idx + (b*NN + n)*KK;
        int cnt = 0, firstv = 0;
        for (int j0 = 0; j0 < NN && cnt < KK; j0 += 32) {
            int j = j0 + lane;
            float dx = sx[j]-qx, dy = sy[j]-qy, dz = sz[j]-qz;
            bool hit = (dx*dx + dy*dy + dz*dz) < R2;
            unsigned m = __ballot_sync(0xffffffffu, hit);
            if (m != 0u && cnt == 0) firstv = j0 + __ffs(m) - 1;
            if (hit) {
                int pos = cnt + __popc(m & ((1u << lane) - 1u));
                if (pos < KK) out[pos] = j;
            }
            cnt += __popc(m);
        }
        if (cnt < KK && lane >= cnt && lane < KK) out[lane] = firstv;  // pad (cnt>=1: self-hit)
    }
}

// ---------------- h precompute: weights in registers, f staged transposed ----------------
__global__ void hpre_kernel(const float* __restrict__ p, const float* __restrict__ f,
                            const float* __restrict__ w1) {
    __shared__ float ft[32][CC];        // [j][c], 8KB, 16B-aligned rows
    __shared__ float pt[32][3];
    int b  = blockIdx.x >> 6;           // grid = 8*64 = 512, 256 threads
    int n0 = (blockIdx.x & 63) * 32;
    int t  = threadIdx.x;
    int o  = t & 63, sub = t >> 6;
    float wp0 = w1[o*67], wp1 = w1[o*67+1], wp2 = w1[o*67+2];
    float wf[64];
    #pragma unroll
    for (int c = 0; c < 64; c++) wf[c] = w1[o*67 + 3 + c];
    // stage: lanes walk c (conflict-free STS); strided global read is L2-cheap (4MB tensor)
    for (int i = t; i < CC*32; i += 256) {
        int c = i & 63, j = i >> 6;
        ft[j][c] = f[(b*CC + c)*NN + n0 + j];
    }
    for (int i = t; i < 96; i += 256) pt[i/3][i%3] = p[(b*NN + n0)*3 + i];
    __syncthreads();
    for (int j = sub; j < 32; j += 4) {
        float acc = wp0*pt[j][0] + wp1*pt[j][1] + wp2*pt[j][2];
        const float4* f4 = (const float4*)ft[j];        // broadcast LDS.128
        #pragma unroll
        for (int i4 = 0; i4 < 16; i4++) {
            float4 v = f4[i4];
            acc += wf[4*i4]*v.x + wf[4*i4+1]*v.y + wf[4*i4+2]*v.z + wf[4*i4+3]*v.w;
        }
        d_h[(b*NN + n0 + j)*CC + o] = acc;
    }
}

// ---------------- gather + max_k + BN1 stats ----------------
__global__ void group_kernel(const float* __restrict__ p, const float* __restrict__ w1) {
    __shared__ int   sidx[16][KK];
    __shared__ float spc[16][3];
    __shared__ float sw1p[CC][3];
    __shared__ float rsum[4][CC], rsq[4][CC];
    int t    = threadIdx.x;            // 256
    int base = blockIdx.x * 16;        // grid = 1024
    int b    = base / NN;
    for (int i = t; i < 16*KK; i += 256) {
        int pt_ = i >> 4, k = i & 15;
        sidx[pt_][k] = d_idx[(base + pt_)*KK + k];
    }
    if (t < 48) { int j = t/3, d = t%3; spc[j][d] = p[(base + j)*3 + d]; }
    if (t < CC*3) sw1p[t/3][t%3] = w1[(t/3)*67 + (t%3)];
    __syncthreads();
    int o = t & 63, pg = t >> 6;
    float w0 = sw1p[o][0], w1c = sw1p[o][1], w2c = sw1p[o][2];
    float ssum = 0.f, ssq = 0.f;
    for (int j = pg; j < 16; j += 4) {
        float q  = w0*spc[j][0] + w1c*spc[j][1] + w2c*spc[j][2];
        float mx = -1e30f;
        #pragma unroll
        for (int k = 0; k < KK; k++) {
            int nb  = sidx[j][k];
            float v = d_h[(b*NN + nb)*CC + o] - q;
            mx = fmaxf(mx, v);
            ssum += v;
            ssq  += v*v;
        }
        d_xmax[(base + j)*CC + o] = mx;
    }
    rsum[pg][o] = ssum; rsq[pg][o] = ssq;
    __syncthreads();
    if (t < CC) {
        float s = rsum[0][t]+rsum[1][t]+rsum[2][t]+rsum[3][t];
        float q = rsq[0][t]+rsq[1][t]+rsq[2][t]+rsq[3][t];
        atomicAdd(&d_stats[t],      s);
        atomicAdd(&d_stats[CC + t], q);
    }
}

__global__ void fin1_kernel(const float* __restrict__ g1, const float* __restrict__ b1) {
    int o = threadIdx.x;  // 64
    float cnt  = (float)(BB*NN*KK);
    float mean = d_stats[o] / cnt;
    float var  = d_stats[CC + o] / cnt - mean*mean;
    float s = g1[o] * rsqrtf(var + EPSV);
    d_sb[o]      = s;
    d_sb[CC + o] = b1[o] - mean*s;
}

// ---------------- mlp2: 4-point staging, float4 broadcast LDS ----------------
__global__ void mlp2_kernel() {
    __shared__ float a[4][CC];
    int t    = threadIdx.x;            // 256, thread = output channel m
    int base = blockIdx.x * 32;        // grid = 512
    float w[64];
    #pragma unroll
    for (int c = 0; c < 64; c++) w[c] = d_w2T[c*MIDD + t];
    float ssum = 0.f, ssq = 0.f;
    int sub = t >> 6, cc_ = t & 63;
    for (int p4 = 0; p4 < 8; p4++) {
        int pidx = base + p4*4 + sub;
        float v = d_sb[cc_]*d_xmax[pidx*CC + cc_] + d_sb[CC + cc_];
        __syncthreads();                        // previous iter's reads done
        a[sub][cc_] = fmaxf(v, 0.f);
        __syncthreads();
        #pragma unroll
        for (int s2 = 0; s2 < 4; s2++) {
            const float4* a4 = (const float4*)a[s2];
            float acc = 0.f;
            #pragma unroll
            for (int i = 0; i < 16; i++) {
                float4 x = a4[i];
                acc += w[4*i]*x.x + w[4*i+1]*x.y + w[4*i+2]*x.z + w[4*i+3]*x.w;
            }
            d_y[(base + p4*4 + s2)*MIDD + t] = acc;
            ssum += acc; ssq += acc*acc;
        }
    }
    atomicAdd(&d_stats[128 + t], ssum);
    atomicAdd(&d_stats[384 + t], ssq);
}

__global__ void fin2_kernel(const float* __restrict__ g2, const float* __restrict__ b2) {
    int m = threadIdx.x;  // 256
    float cnt  = (float)(BB*NN);
    float mean = d_stats[128 + m] / cnt;
    float var  = d_stats[384 + m] / cnt - mean*mean;
    float s = g2[m] * rsqrtf(var + EPSV);
    d_sb[128 + m] = s;
    d_sb[384 + m] = b2[m] - mean*s;
}

// ---------------- mlp3: 4-point staging, c-sliced weights, float4 broadcast LDS ----------------
__global__ void mlp3_kernel() {
    __shared__ float yb[4][MIDD];       // 4KB
    __shared__ float part[4][4][CC];    // [pt][cs][o] 4KB
    __shared__ float zsm[CC][33];       // 8.25KB
    int t    = threadIdx.x;             // 256
    int o    = t & 63, cs = t >> 6;
    int base = blockIdx.x * 32;         // grid = 512
    int b    = base / NN, n0 = base % NN;
    float wreg[64];
    #pragma unroll
    for (int cq = 0; cq < 64; cq++) wreg[cq] = d_w3T[(cs*64 + cq)*CC + o];
    float ssum = 0.f, ssq = 0.f;
    for (int p4 = 0; p4 < 8; p4++) {
        float vr[4];
        #pragma unroll
        for (int r = 0; r < 4; r++) {
            int i = r*256 + t;          // 0..1023
            int pt_ = i >> 8, m = i & 255;
            float v = d_sb[128 + m]*d_y[(base + p4*4 + pt_)*MIDD + m] + d_sb[384 + m];
            vr[r] = fmaxf(v, 0.f);
        }
        __syncthreads();                // previous iter's yb reads done
        #pragma unroll
        for (int r = 0; r < 4; r++) {
            int i = r*256 + t;
            ((float*)yb)[i] = vr[r];
        }
        __syncthreads();
        #pragma unroll
        for (int pt_ = 0; pt_ < 4; pt_++) {
            const float4* y4 = (const float4*)&yb[pt_][cs*64];   // broadcast LDS.128
            float acc = 0.f;
            #pragma unroll
            for (int i = 0; i < 16; i++) {
                float4 x = y4[i];
                acc += wreg[4*i]*x.x + wreg[4*i+1]*x.y + wreg[4*i+2]*x.z + wreg[4*i+3]*x.w;
            }
            part[pt_][cs][o] = acc;
        }
        __syncthreads();
        {
            int pt_ = t >> 6;
            float z = part[pt_][0][o] + part[pt_][1][o] + part[pt_][2][o] + part[pt_][3][o];
            zsm[o][p4*4 + pt_] = z;
            ssum += z; ssq += z*z;
        }
    }
    __syncthreads();
    for (int i = t; i < CC*32; i += 256) {
        int r = i >> 5, cl = i & 31;
        d_z[(b*CC + r)*NN + n0 + cl] = zsm[r][cl];
    }
    atomicAdd(&d_stats[640 + o], ssum);
    atomicAdd(&d_stats[704 + o], ssq);
}

__global__ void fin3_kernel(const float* __restrict__ g3, const float* __restrict__ b3) {
    int o = threadIdx.x;  // 64
    float cnt  = (float)(BB*NN);
    float mean = d_stats[640 + o] / cnt;
    float var  = d_stats[704 + o] / cnt - mean*mean;
    float s = g3[o] * rsqrtf(var + EPSV);
    d_sb[640 + o] = s;
    d_sb[704 + o] = b3[o] - mean*s;
}

// ---------------- epilogue ----------------
__global__ void out_kernel(const float* __restrict__ f, float* __restrict__ out) {
    int i = blockIdx.x * blockDim.x + threadIdx.x;
    int c = (i >> 11) & 63;
    float v = d_sb[640 + c]*d_z[i] + d_sb[704 + c] + f[i];
    out[i] = fmaxf(v, 0.f);
}

// ---------------- launch ----------------
extern "C" void kernel_launch(void* const* d_in, const int* in_sizes, int n_in,
                              void* d_out, int out_size) {
    const float* p  = (const float*)d_in[0];
    const float* f  = (const float*)d_in[1];
    const float* w1 = (const float*)d_in[2];
    const float* g1 = (const float*)d_in[3];
    const float* b1 = (const float*)d_in[4];
    const float* w2 = (const float*)d_in[5];
    const float* g2 = (const float*)d_in[6];
    const float* b2 = (const float*)d_in[7];
    const float* w3 = (const float*)d_in[8];
    const float* g3 = (const float*)d_in[9];
    const float* b3 = (const float*)d_in[10];
    float* out = (float*)d_out;

    prep_kernel <<<64, 256>>>(w2, w3);
    bq_kernel   <<<BB*32, 256>>>(p);
    hpre_kernel <<<BB*(NN/32), 256>>>(p, f, w1);
    group_kernel<<<BB*NN/16, 256>>>(p, w1);
    fin1_kernel <<<1, 64>>>(g1, b1);
    mlp2_kernel <<<BB*NN/32, 256>>>();
    fin2_kernel <<<1, 256>>>(g2, b2);
    mlp3_kernel <<<BB*NN/32, 256>>>();
    fin3_kernel <<<1, 64>>>(g3, b3);
    out_kernel  <<<BB*CC*NN/256, 256>>>(f, out);
}

// round 3
// speedup vs baseline: 1.5455x; 1.1058x over previous
#include <cuda_runtime.h>

#define BB   8
#define NN   2048
#define CC   64
#define MIDD 256
#define KK   16
#define R2   0.0225f
#define EPSV 1e-5f

// ---------------- device scratch ----------------
__device__ float d_h[BB*NN*CC];        // h[b][n][o]
__device__ int   d_idx[BB*NN*KK];
__device__ float d_xmax[BB*NN*CC];
__device__ float d_y[BB*NN*MIDD];
__device__ float d_z[BB*CC*NN];
__device__ float d_w2T[MIDD*CC];       // [c][m]
__device__ float d_w3T[CC*MIDD];       // [c][o]
__device__ float d_stats[768];         // sum1[64] sq1[64] sum2[256] sq2[256] sum3[64] sq3[64]

// =========================================================================
// FRONT kernel: blocks [0,256) ball-query | [256,768) h-precompute | [768,832) prep
// =========================================================================
__global__ void front_kernel(const float* __restrict__ p, const float* __restrict__ f,
                             const float* __restrict__ w1, const float* __restrict__ w2,
                             const float* __restrict__ w3) {
    __shared__ __align__(16) char smem[24576];
    int t = threadIdx.x;                           // 256 threads

    if (blockIdx.x < 256) {
        // ---------- ball query: warp-cooperative ballot scan ----------
        float* sx = (float*)smem;
        float* sy = sx + NN;
        float* sz = sy + NN;
        int b   = blockIdx.x >> 5;
        int blk = blockIdx.x & 31;
        const float* pb = p + b*NN*3;
        for (int j = t; j < NN; j += 256) {
            sx[j] = pb[3*j]; sy[j] = pb[3*j+1]; sz[j] = pb[3*j+2];
        }
        __syncthreads();
        int w = t >> 5, lane = t & 31;
        int qbase = blk*64 + w*8;
        for (int q = 0; q < 8; q++) {
            int n = qbase + q;
            float qx = sx[n], qy = sy[n], qz = sz[n];
            int* out = d_idx + (b*NN + n)*KK;
            int cnt = 0, firstv = 0;
            for (int j0 = 0; j0 < NN && cnt < KK; j0 += 32) {
                int j = j0 + lane;
                float dx = sx[j]-qx, dy = sy[j]-qy, dz = sz[j]-qz;
                bool hit = (dx*dx + dy*dy + dz*dz) < R2;
                unsigned m = __ballot_sync(0xffffffffu, hit);
                if (m != 0u && cnt == 0) firstv = j0 + __ffs(m) - 1;
                if (hit) {
                    int pos = cnt + __popc(m & ((1u << lane) - 1u));
                    if (pos < KK) out[pos] = j;
                }
                cnt += __popc(m);
            }
            if (cnt < KK && lane >= cnt && lane < KK) out[lane] = firstv;
        }
    } else if (blockIdx.x < 768) {
        // ---------- h precompute ----------
        int id = blockIdx.x - 256;                 // 0..511
        float (*ft)[CC] = (float(*)[CC])smem;      // [32][64] 8KB
        float (*pt)[3]  = (float(*)[3])(smem + 32*CC*4);
        int b  = id >> 6;
        int n0 = (id & 63) * 32;
        int o  = t & 63, sub = t >> 6;
        float wp0 = w1[o*67], wp1 = w1[o*67+1], wp2 = w1[o*67+2];
        float wf[64];
        #pragma unroll
        for (int c = 0; c < 64; c++) wf[c] = w1[o*67 + 3 + c];
        for (int i = t; i < CC*32; i += 256) {
            int c = i & 63, j = i >> 6;
            ft[j][c] = f[(b*CC + c)*NN + n0 + j];
        }
        for (int i = t; i < 96; i += 256) pt[i/3][i%3] = p[(b*NN + n0)*3 + i];
        __syncthreads();
        for (int j = sub; j < 32; j += 4) {
            float acc = wp0*pt[j][0] + wp1*pt[j][1] + wp2*pt[j][2];
            const float4* f4 = (const float4*)ft[j];
            #pragma unroll
            for (int i4 = 0; i4 < 16; i4++) {
                float4 v = f4[i4];
                acc += wf[4*i4]*v.x + wf[4*i4+1]*v.y + wf[4*i4+2]*v.z + wf[4*i4+3]*v.w;
            }
            d_h[(b*NN + n0 + j)*CC + o] = acc;
        }
    } else {
        // ---------- prep: zero stats + transpose weights ----------
        int i = (blockIdx.x - 768)*256 + t;        // 0..16383
        if (i < 768) d_stats[i] = 0.f;
        {   int m = i / CC, c = i % CC;  d_w2T[c*MIDD + m] = w2[i]; }
        {   int o = i / MIDD, c = i % MIDD;  d_w3T[c*CC + o] = w3[i]; }
    }
}

// =========================================================================
// group: gather (float4, 16-way MLP) + max_k + BN1 stats
// =========================================================================
__global__ void group_kernel(const float* __restrict__ p, const float* __restrict__ w1) {
    __shared__ int   sidx[16][KK];                 // 1KB
    __shared__ float spc[16][3];
    __shared__ float sw1p[CC][3];
    __shared__ float rsum[16][CC+1], rsq[16][CC+1]; // padded vs bank conflicts, 8.3KB
    int t    = threadIdx.x;                        // 256
    int base = blockIdx.x * 16;                    // grid = 1024
    int b    = base / NN;
    for (int i = t; i < 16*KK; i += 256) {
        int pt_ = i >> 4, k = i & 15;
        sidx[pt_][k] = d_idx[(base + pt_)*KK + k];
    }
    if (t < 48) { int j = t/3, d = t%3; spc[j][d] = p[(base + j)*3 + d]; }
    if (t < CC*3) sw1p[t/3][t%3] = w1[(t/3)*67 + (t%3)];
    __syncthreads();
    int j = t >> 4, o4 = t & 15;                   // point j, channels 4*o4..4*o4+3
    float px = spc[j][0], py = spc[j][1], pz = spc[j][2];
    float q0 = sw1p[4*o4+0][0]*px + sw1p[4*o4+0][1]*py + sw1p[4*o4+0][2]*pz;
    float q1 = sw1p[4*o4+1][0]*px + sw1p[4*o4+1][1]*py + sw1p[4*o4+1][2]*pz;
    float q2 = sw1p[4*o4+2][0]*px + sw1p[4*o4+2][1]*py + sw1p[4*o4+2][2]*pz;
    float q3 = sw1p[4*o4+3][0]*px + sw1p[4*o4+3][1]*py + sw1p[4*o4+3][2]*pz;
    const float4* h4 = (const float4*)d_h;
    float mx0=-1e30f, mx1=-1e30f, mx2=-1e30f, mx3=-1e30f;
    float s0=0.f,s1=0.f,s2=0.f,s3=0.f, sq0=0.f,sq1=0.f,sq2=0.f,sq3=0.f;
    #pragma unroll
    for (int k = 0; k < KK; k++) {
        int nb = sidx[j][k];
        float4 v = h4[(b*NN + nb)*16 + o4];        // 16 independent LDG.128
        float v0 = v.x - q0, v1 = v.y - q1, v2 = v.z - q2, v3 = v.w - q3;
        mx0 = fmaxf(mx0, v0); mx1 = fmaxf(mx1, v1);
        mx2 = fmaxf(mx2, v2); mx3 = fmaxf(mx3, v3);
        s0 += v0; s1 += v1; s2 += v2; s3 += v3;
        sq0 += v0*v0; sq1 += v1*v1; sq2 += v2*v2; sq3 += v3*v3;
    }
    ((float4*)d_xmax)[(base + j)*16 + o4] = make_float4(mx0, mx1, mx2, mx3);
    rsum[j][4*o4+0]=s0; rsum[j][4*o4+1]=s1; rsum[j][4*o4+2]=s2; rsum[j][4*o4+3]=s3;
    rsq [j][4*o4+0]=sq0; rsq[j][4*o4+1]=sq1; rsq[j][4*o4+2]=sq2; rsq[j][4*o4+3]=sq3;
    __syncthreads();
    if (t < CC) {
        float s = 0.f, q = 0.f;
        #pragma unroll
        for (int jj = 0; jj < 16; jj++) { s += rsum[jj][t]; q += rsq[jj][t]; }
        atomicAdd(&d_stats[t],      s);
        atomicAdd(&d_stats[CC + t], q);
    }
}

// =========================================================================
// mlp2 (+inline fin1): y = w2 @ relu(bn1(xmax)), BN2 stats
// =========================================================================
__global__ void mlp2_kernel(const float* __restrict__ g1, const float* __restrict__ b1) {
    __shared__ float a[4][CC];
    int t    = threadIdx.x;                        // 256, thread = output channel m
    int base = blockIdx.x * 32;                    // grid = 512
    int sub = t >> 6, cc_ = t & 63;
    // inline fin1 (per-thread, registers)
    float cnt1 = (float)(BB*NN*KK);
    float mean1 = d_stats[cc_] / cnt1;
    float var1  = d_stats[CC + cc_] / cnt1 - mean1*mean1;
    float s1v = g1[cc_] * rsqrtf(var1 + EPSV);
    float t1v = b1[cc_] - mean1*s1v;
    float w[64];
    #pragma unroll
    for (int c = 0; c < 64; c++) w[c] = d_w2T[c*MIDD + t];
    float ssum = 0.f, ssq = 0.f;
    for (int p4 = 0; p4 < 8; p4++) {
        int pidx = base + p4*4 + sub;
        float v = s1v*d_xmax[pidx*CC + cc_] + t1v;
        __syncthreads();
        a[sub][cc_] = fmaxf(v, 0.f);
        __syncthreads();
        #pragma unroll
        for (int s2 = 0; s2 < 4; s2++) {
            const float4* a4 = (const float4*)a[s2];
            float acc = 0.f;
            #pragma unroll
            for (int i = 0; i < 16; i++) {
                float4 x = a4[i];
                acc += w[4*i]*x.x + w[4*i+1]*x.y + w[4*i+2]*x.z + w[4*i+3]*x.w;
            }
            d_y[(base + p4*4 + s2)*MIDD + t] = acc;
            ssum += acc; ssq += acc*acc;
        }
    }
    atomicAdd(&d_stats[128 + t], ssum);
    atomicAdd(&d_stats[384 + t], ssq);
}

// =========================================================================
// mlp3 (+inline fin2): z = w3 @ relu(bn2(y)), BN3 stats, output (B,C,N)
// =========================================================================
__global__ void mlp3_kernel(const float* __restrict__ g2, const float* __restrict__ b2) {
    __shared__ float yb[4][MIDD];
    __shared__ float part[4][4][CC];
    __shared__ float zsm[CC][33];
    int t    = threadIdx.x;                        // 256
    int o    = t & 63, cs = t >> 6;
    int base = blockIdx.x * 32;                    // grid = 512
    int b    = base / NN, n0 = base % NN;
    // inline fin2 (m == t for all staged reads)
    float cnt2 = (float)(BB*NN);
    float mean2 = d_stats[128 + t] / cnt2;
    float var2  = d_stats[384 + t] / cnt2 - mean2*mean2;
    float s2v = g2[t] * rsqrtf(var2 + EPSV);
    float t2v = b2[t] - mean2*s2v;
    float wreg[64];
    #pragma unroll
    for (int cq = 0; cq < 64; cq++) wreg[cq] = d_w3T[(cs*64 + cq)*CC + o];
    float ssum = 0.f, ssq = 0.f;
    for (int p4 = 0; p4 < 8; p4++) {
        float vr[4];
        #pragma unroll
        for (int r = 0; r < 4; r++) {
            float v = s2v*d_y[(base + p4*4 + r)*MIDD + t] + t2v;
            vr[r] = fmaxf(v, 0.f);
        }
        __syncthreads();
        #pragma unroll
        for (int r = 0; r < 4; r++) yb[r][t] = vr[r];
        __syncthreads();
        #pragma unroll
        for (int pt_ = 0; pt_ < 4; pt_++) {
            const float4* y4 = (const float4*)&yb[pt_][cs*64];
            float acc = 0.f;
            #pragma unroll
            for (int i = 0; i < 16; i++) {
                float4 x = y4[i];
                acc += wreg[4*i]*x.x + wreg[4*i+1]*x.y + wreg[4*i+2]*x.z + wreg[4*i+3]*x.w;
            }
            part[pt_][cs][o] = acc;
        }
        __syncthreads();
        {
            int pt_ = t >> 6;
            float z = part[pt_][0][o] + part[pt_][1][o] + part[pt_][2][o] + part[pt_][3][o];
            zsm[o][p4*4 + pt_] = z;
            ssum += z; ssq += z*z;
        }
    }
    __syncthreads();
    for (int i = t; i < CC*32; i += 256) {
        int r = i >> 5, cl = i & 31;
        d_z[(b*CC + r)*NN + n0 + cl] = zsm[r][cl];
    }
    atomicAdd(&d_stats[640 + o], ssum);
    atomicAdd(&d_stats[704 + o], ssq);
}

// =========================================================================
// out (+inline fin3): out = relu(bn3(z) + f), float4
// =========================================================================
__global__ void out_kernel(const float* __restrict__ f, const float* __restrict__ g3,
                           const float* __restrict__ b3, float* __restrict__ out) {
    int i4 = blockIdx.x * 256 + threadIdx.x;       // grid = 1024
    int i  = i4 * 4;
    int c  = (i >> 11) & 63;                       // uniform per block
    float cnt3 = (float)(BB*NN);
    float mean3 = d_stats[640 + c] / cnt3;
    float var3  = d_stats[704 + c] / cnt3 - mean3*mean3;
    float s3v = g3[c] * rsqrtf(var3 + EPSV);
    float t3v = b3[c] - mean3*s3v;
    float4 z = ((const float4*)d_z)[i4];
    float4 ff = ((const float4*)f)[i4];
    float4 r;
    r.x = fmaxf(s3v*z.x + t3v + ff.x, 0.f);
    r.y = fmaxf(s3v*z.y + t3v + ff.y, 0.f);
    r.z = fmaxf(s3v*z.z + t3v + ff.z, 0.f);
    r.w = fmaxf(s3v*z.w + t3v + ff.w, 0.f);
    ((float4*)out)[i4] = r;
}

// ---------------- launch: 5 kernels ----------------
extern "C" void kernel_launch(void* const* d_in, const int* in_sizes, int n_in,
                              void* d_out, int out_size) {
    const float* p  = (const float*)d_in[0];
    const float* f  = (const float*)d_in[1];
    const float* w1 = (const float*)d_in[2];
    const float* g1 = (const float*)d_in[3];
    const float* b1 = (const float*)d_in[4];
    const float* w2 = (const float*)d_in[5];
    const float* g2 = (const float*)d_in[6];
    const float* b2 = (const float*)d_in[7];
    const float* w3 = (const float*)d_in[8];
    const float* g3 = (const float*)d_in[9];
    const float* b3 = (const float*)d_in[10];
    float* out = (float*)d_out;

    front_kernel<<<832, 256>>>(p, f, w1, w2, w3);
    group_kernel<<<BB*NN/16, 256>>>(p, w1);
    mlp2_kernel <<<BB*NN/32, 256>>>(g1, b1);
    mlp3_kernel <<<BB*NN/32, 256>>>(g2, b2);
    out_kernel  <<<BB*CC*NN/1024, 256>>>(f, g3, b3, out);
}